// round 1
// baseline (speedup 1.0000x reference)
#include <cuda_runtime.h>
#include <math.h>

#define Bsz   512
#define Tsz   256
#define Fsz   128
#define Hsz   512
#define FFsz  1024
#define OUTsz 64
#define H3    (3 * Hsz)
#define BT    (Bsz * Tsz)
#define PADV  (-999.0f)

// ---------------- scratch (static device globals; no allocations) ----------------
__device__ float g_GI[(size_t)BT * H3];     // 805 MB: x @ W_ih^T + b_ih
__device__ float g_ffin[(size_t)BT * Hsz];  // 256 MB: masked rnn_out (0 on pad)
__device__ float g_hid[(size_t)BT * FFsz];  // 512 MB: relu(ffin @ W1 + b1)
__device__ float g_h[2][Bsz * Hsz];         // double-buffered hidden state

// ---------------- packed f32x2 helpers (Blackwell FFMA2 path) ----------------
__device__ __forceinline__ unsigned long long pack2(float x, float y) {
    unsigned long long r;
    asm("mov.b64 %0,{%1,%2};" : "=l"(r) : "f"(x), "f"(y));
    return r;
}
__device__ __forceinline__ void fma2(unsigned long long& d, unsigned long long a,
                                     unsigned long long b) {
    asm("fma.rn.f32x2 %0,%1,%2,%0;" : "+l"(d) : "l"(a), "l"(b));
}
__device__ __forceinline__ void unpack2(unsigned long long v, float& x, float& y) {
    asm("mov.b64 {%0,%1},%2;" : "=f"(x), "=f"(y) : "l"(v));
}

// ---------------- init ----------------
__global__ void zero_h_kernel() {
    int i = blockIdx.x * blockDim.x + threadIdx.x;
    if (i < Bsz * Hsz) g_h[0][i] = 0.0f;
}

// ---------------- generic 128x128 tiled SGEMM: C = A @ B(^T) + bias, opt relu ----
// A: [M, KDIM] row-major. If BTRANS: Bm is [NDIM, KDIM] (use Bm^T). Else Bm is
// [KDIM, NDIM]. SKIP: tile rows all belong to one batch (128 | Tsz); if the
// whole tile is past seq_len, skip (consumer masks / never reads it).
template <int KDIM, int NDIM, bool BTRANS, bool RELU, bool SKIP>
__global__ __launch_bounds__(256) void sgemm128(const float* __restrict__ A,
                                                const float* __restrict__ Bm,
                                                const float* __restrict__ bias,
                                                float* __restrict__ C,
                                                const int* __restrict__ seq) {
    const int m0 = blockIdx.x * 128;
    const int n0 = blockIdx.y * 128;
    if (SKIP) {
        int b  = m0 / Tsz;
        int t0 = m0 % Tsz;
        if (t0 >= seq[b]) return;
    }
    __shared__ float As[16][128];
    __shared__ float Bs[16][128];
    const int tid  = threadIdx.x;
    const int tx   = tid % 16, ty = tid / 16;
    const int row0 = ty * 8, col0 = tx * 8;

    unsigned long long acc[8][4];
#pragma unroll
    for (int i = 0; i < 8; i++)
#pragma unroll
        for (int j = 0; j < 4; j++) acc[i][j] = 0ULL;

    for (int k0 = 0; k0 < KDIM; k0 += 16) {
        // A tile: 128 rows x 16 k, transposed into As[k][m]
#pragma unroll
        for (int l = 0; l < 2; l++) {
            int idx = tid + l * 256;
            int r = idx >> 2, c4 = (idx & 3) * 4;
            float4 v = *(const float4*)&A[(size_t)(m0 + r) * KDIM + k0 + c4];
            As[c4 + 0][r] = v.x; As[c4 + 1][r] = v.y;
            As[c4 + 2][r] = v.z; As[c4 + 3][r] = v.w;
        }
        if (BTRANS) {
#pragma unroll
            for (int l = 0; l < 2; l++) {
                int idx = tid + l * 256;
                int n = idx >> 2, c4 = (idx & 3) * 4;
                float4 v = *(const float4*)&Bm[(size_t)(n0 + n) * KDIM + k0 + c4];
                Bs[c4 + 0][n] = v.x; Bs[c4 + 1][n] = v.y;
                Bs[c4 + 2][n] = v.z; Bs[c4 + 3][n] = v.w;
            }
        } else {
#pragma unroll
            for (int l = 0; l < 2; l++) {
                int idx = tid + l * 256;
                int k = idx >> 5, c4 = (idx & 31) * 4;
                float4 v = *(const float4*)&Bm[(size_t)(k0 + k) * NDIM + n0 + c4];
                *(float4*)&Bs[k][c4] = v;
            }
        }
        __syncthreads();
#pragma unroll
        for (int k = 0; k < 16; k++) {
            float4 a0 = *(const float4*)&As[k][row0];
            float4 a1 = *(const float4*)&As[k][row0 + 4];
            unsigned long long bb[4];
#pragma unroll
            for (int j = 0; j < 4; j++)
                bb[j] = *(const unsigned long long*)&Bs[k][col0 + j * 2];
            float av[8] = {a0.x, a0.y, a0.z, a0.w, a1.x, a1.y, a1.z, a1.w};
#pragma unroll
            for (int i = 0; i < 8; i++) {
                unsigned long long ad = pack2(av[i], av[i]);
#pragma unroll
                for (int j = 0; j < 4; j++) fma2(acc[i][j], ad, bb[j]);
            }
        }
        __syncthreads();
    }
#pragma unroll
    for (int i = 0; i < 8; i++) {
        float out[8];
#pragma unroll
        for (int j = 0; j < 4; j++) unpack2(acc[i][j], out[j * 2], out[j * 2 + 1]);
#pragma unroll
        for (int j = 0; j < 8; j++) {
            float v = out[j] + bias[n0 + col0 + j];
            if (RELU) v = fmaxf(v, 0.0f);
            out[j] = v;
        }
        float4* cp = (float4*)&C[(size_t)(m0 + row0 + i) * NDIM + n0 + col0];
        cp[0] = make_float4(out[0], out[1], out[2], out[3]);
        cp[1] = make_float4(out[4], out[5], out[6], out[7]);
    }
}

// ---------------- GRU step: gh = h @ W_hh^T (+b_hh), gates, h update ----------
// Block tile: 64 batch rows x 32 hidden units x 3 gates. Grid (8, 16).
// Double-buffered h to avoid read/write races across blocks within a step.
__global__ __launch_bounds__(256) void gru_step_kernel(int t, int pp,
                                                       const float* __restrict__ W_hh,
                                                       const float* __restrict__ b_hh,
                                                       const int* __restrict__ seq) {
    __shared__ float As[32][64];       // h tile, transposed [k][m]
    __shared__ float Bs[3][32][32];    // W_hh tiles per gate, [k][n]
    const float* hin  = g_h[pp];
    float*       hout = g_h[pp ^ 1];
    const int m0 = blockIdx.x * 64;    // batch offset
    const int n0 = blockIdx.y * 32;    // hidden offset
    const int tid = threadIdx.x;
    const int tx = tid % 16, ty = tid / 16;

    unsigned long long aR[4], aZ[4], aN[4];
#pragma unroll
    for (int i = 0; i < 4; i++) { aR[i] = 0ULL; aZ[i] = 0ULL; aN[i] = 0ULL; }

    for (int k0 = 0; k0 < Hsz; k0 += 32) {
#pragma unroll
        for (int l = 0; l < 2; l++) {
            int idx = tid + l * 256;
            int r = idx >> 3, c4 = (idx & 7) * 4;
            float4 v = *(const float4*)&hin[(size_t)(m0 + r) * Hsz + k0 + c4];
            As[c4 + 0][r] = v.x; As[c4 + 1][r] = v.y;
            As[c4 + 2][r] = v.z; As[c4 + 3][r] = v.w;
        }
        {
            int n = tid >> 3, c4 = (tid & 7) * 4;
#pragma unroll
            for (int g = 0; g < 3; g++) {
                float4 v = *(const float4*)&W_hh[(size_t)(g * Hsz + n0 + n) * Hsz + k0 + c4];
                Bs[g][c4 + 0][n] = v.x; Bs[g][c4 + 1][n] = v.y;
                Bs[g][c4 + 2][n] = v.z; Bs[g][c4 + 3][n] = v.w;
            }
        }
        __syncthreads();
#pragma unroll
        for (int k = 0; k < 32; k++) {
            float4 a = *(const float4*)&As[k][ty * 4];
            unsigned long long br = *(const unsigned long long*)&Bs[0][k][tx * 2];
            unsigned long long bz = *(const unsigned long long*)&Bs[1][k][tx * 2];
            unsigned long long bn = *(const unsigned long long*)&Bs[2][k][tx * 2];
            float av[4] = {a.x, a.y, a.z, a.w};
#pragma unroll
            for (int i = 0; i < 4; i++) {
                unsigned long long ad = pack2(av[i], av[i]);
                fma2(aR[i], ad, br);
                fma2(aZ[i], ad, bz);
                fma2(aN[i], ad, bn);
            }
        }
        __syncthreads();
    }

#pragma unroll
    for (int i = 0; i < 4; i++) {
        int m = m0 + ty * 4 + i;
        int valid = (t < seq[m]) ? 1 : 0;
        size_t bt = (size_t)m * Tsz + t;
        float gr[2], gz[2], gn[2];
        unpack2(aR[i], gr[0], gr[1]);
        unpack2(aZ[i], gz[0], gz[1]);
        unpack2(aN[i], gn[0], gn[1]);
#pragma unroll
        for (int j = 0; j < 2; j++) {
            int n = n0 + tx * 2 + j;
            float ghr = gr[j] + b_hh[n];
            float ghz = gz[j] + b_hh[Hsz + n];
            float ghn = gn[j] + b_hh[2 * Hsz + n];
            size_t gib = bt * (size_t)H3 + n;
            float gir = g_GI[gib];
            float giz = g_GI[gib + Hsz];
            float gin = g_GI[gib + 2 * Hsz];
            float r  = 1.0f / (1.0f + __expf(-(gir + ghr)));
            float z  = 1.0f / (1.0f + __expf(-(giz + ghz)));
            float nn = tanhf(gin + r * ghn);
            float hp = hin[(size_t)m * Hsz + n];
            float hnew = (1.0f - z) * nn + z * hp;
            hout[(size_t)m * Hsz + n] = valid ? hnew : hp;
            g_ffin[bt * Hsz + n]      = valid ? hnew : 0.0f;
        }
    }
}

// ---------------- output GEMM: Y = hid @ W2 + b2, PAD-masked --------------------
// Block tile: 128 bt-rows x 64 (=OUT) cols. Grid (1024).
__global__ __launch_bounds__(256) void out_gemm_kernel(const float* __restrict__ W2,
                                                       const float* __restrict__ b2,
                                                       const int* __restrict__ seq,
                                                       float* __restrict__ Y) {
    const int m0 = blockIdx.x * 128;
    const int b  = m0 / Tsz;
    const int t0 = m0 % Tsz;
    const int tid = threadIdx.x;
    const int slen = seq[b];
    if (t0 >= slen) {
        float4 pv = make_float4(PADV, PADV, PADV, PADV);
#pragma unroll
        for (int l = 0; l < 8; l++) {
            int idx = tid + l * 256;  // float4 index in 128x64 tile
            *(float4*)&Y[(size_t)(m0 + (idx >> 4)) * OUTsz + (idx & 15) * 4] = pv;
        }
        return;
    }
    __shared__ float As[32][128];
    __shared__ float Bs[32][64];
    const int tx = tid % 16, ty = tid / 16;
    const int row0 = ty * 8, col0 = tx * 4;
    unsigned long long acc[8][2];
#pragma unroll
    for (int i = 0; i < 8; i++) { acc[i][0] = 0ULL; acc[i][1] = 0ULL; }

    for (int k0 = 0; k0 < FFsz; k0 += 32) {
#pragma unroll
        for (int l = 0; l < 4; l++) {
            int idx = tid + l * 256;
            int r = idx >> 3, c4 = (idx & 7) * 4;
            float4 v = *(const float4*)&g_hid[(size_t)(m0 + r) * FFsz + k0 + c4];
            As[c4 + 0][r] = v.x; As[c4 + 1][r] = v.y;
            As[c4 + 2][r] = v.z; As[c4 + 3][r] = v.w;
        }
#pragma unroll
        for (int l = 0; l < 2; l++) {
            int idx = tid + l * 256;
            int k = idx >> 4, c4 = (idx & 15) * 4;
            *(float4*)&Bs[k][c4] = *(const float4*)&W2[(size_t)(k0 + k) * OUTsz + c4];
        }
        __syncthreads();
#pragma unroll
        for (int k = 0; k < 32; k++) {
            float4 a0 = *(const float4*)&As[k][row0];
            float4 a1 = *(const float4*)&As[k][row0 + 4];
            unsigned long long b0 = *(const unsigned long long*)&Bs[k][col0];
            unsigned long long b1 = *(const unsigned long long*)&Bs[k][col0 + 2];
            float av[8] = {a0.x, a0.y, a0.z, a0.w, a1.x, a1.y, a1.z, a1.w};
#pragma unroll
            for (int i = 0; i < 8; i++) {
                unsigned long long ad = pack2(av[i], av[i]);
                fma2(acc[i][0], ad, b0);
                fma2(acc[i][1], ad, b1);
            }
        }
        __syncthreads();
    }
#pragma unroll
    for (int i = 0; i < 8; i++) {
        int m = m0 + row0 + i;
        int t = t0 + row0 + i;
        float o[4];
        unpack2(acc[i][0], o[0], o[1]);
        unpack2(acc[i][1], o[2], o[3]);
        float4 v;
        if (t < slen) {
            v = make_float4(o[0] + b2[col0 + 0], o[1] + b2[col0 + 1],
                            o[2] + b2[col0 + 2], o[3] + b2[col0 + 3]);
        } else {
            v = make_float4(PADV, PADV, PADV, PADV);
        }
        *(float4*)&Y[(size_t)m * OUTsz + col0] = v;
    }
}

// ---------------- launch ----------------
extern "C" void kernel_launch(void* const* d_in, const int* in_sizes, int n_in,
                              void* d_out, int out_size) {
    (void)in_sizes; (void)n_in; (void)out_size;
    const float* x    = (const float*)d_in[0];
    const int*   seq  = (const int*)d_in[1];
    const float* W_ih = (const float*)d_in[2];
    const float* W_hh = (const float*)d_in[3];
    const float* b_ih = (const float*)d_in[4];
    const float* b_hh = (const float*)d_in[5];
    const float* W1   = (const float*)d_in[6];
    const float* b1   = (const float*)d_in[7];
    const float* W2   = (const float*)d_in[8];
    const float* b2   = (const float*)d_in[9];
    float* Y = (float*)d_out;

    float *pGI = nullptr, *pFF = nullptr, *pHID = nullptr;
    cudaGetSymbolAddress((void**)&pGI, g_GI);
    cudaGetSymbolAddress((void**)&pFF, g_ffin);
    cudaGetSymbolAddress((void**)&pHID, g_hid);

    // 1) h0 = 0
    zero_h_kernel<<<(Bsz * Hsz + 255) / 256, 256>>>();

    // 2) GI = x @ W_ih^T + b_ih   (full-pad tiles skipped)
    sgemm128<Fsz, H3, true, false, true>
        <<<dim3(BT / 128, H3 / 128), 256>>>(x, W_ih, b_ih, pGI, seq);

    // 3) sequential GRU over T steps (double-buffered h)
    for (int t = 0; t < Tsz; t++) {
        gru_step_kernel<<<dim3(Bsz / 64, Hsz / 32), 256>>>(t, t & 1, W_hh, b_hh, seq);
    }

    // 4) HID = relu(ffin @ W1 + b1)   (full-pad tiles skipped)
    sgemm128<Hsz, FFsz, false, true, true>
        <<<dim3(BT / 128, FFsz / 128), 256>>>(pFF, W1, b1, pHID, seq);

    // 5) Y = hid @ W2 + b2, PAD-masked
    out_gemm_kernel<<<dim3(BT / 128), 256>>>(W2, b2, seq, Y);
}